// round 1
// baseline (speedup 1.0000x reference)
#include <cuda_runtime.h>
#include <math.h>

#define HH 256
#define WW 256
#define HW 65536
#define NB 8
#define NCC 3          // channels 1..3 kept
#define NSLICE 24      // NB*NCC
#define NPIX (NB*HW)   // 524288
#define NFIELD 4       // 0: mask_p, 1: ~mask_p, 2: mask_t, 3: ~mask_t
#define CAP 512        // INF = H + W in reference

// -------- device scratch (no allocations allowed) --------
__device__ unsigned char  g_masks[NPIX];                    // bits 0..2 mask_p cc, 3..5 mask_t cc
__device__ float          g_p[NSLICE * HW];                 // softmax probs, channels 1..3
__device__ unsigned short g_vert[NFIELD * NSLICE * HW];     // vertical 1D distances (<=512)
__device__ int            g_cnt[2 * NSLICE];                // [0..23] p-counts, [24..47] t-counts
__device__ double         g_acc;

// -------- kernel 0: zero accumulators --------
__global__ void k_init() {
    int t = threadIdx.x;
    if (t < 2 * NSLICE) g_cnt[t] = 0;
    if (t == 0) g_acc = 0.0;
}

// -------- kernel 1: softmax + argmax + masks + per-slice counts --------
__global__ void __launch_bounds__(256) k_prep(const float* __restrict__ S,
                                              const float* __restrict__ T) {
    int idx = blockIdx.x * 256 + threadIdx.x;   // 0 .. NPIX-1, block fully inside one b
    int b   = idx >> 16;
    int pix = idx & 0xFFFF;

    const float* s = S + (size_t)b * 4 * HW + pix;
    float s0 = s[0], s1 = s[HW], s2 = s[2 * HW], s3 = s[3 * HW];
    float m  = fmaxf(fmaxf(s0, s1), fmaxf(s2, s3));
    float e0 = expf(s0 - m), e1 = expf(s1 - m), e2 = expf(s2 - m), e3 = expf(s3 - m);
    float inv = 1.0f / (e0 + e1 + e2 + e3);
    float p1 = e1 * inv, p2 = e2 * inv, p3 = e3 * inv;

    const float* t = T + (size_t)b * 4 * HW + pix;
    float t0 = t[0], t1 = t[HW], t2 = t[2 * HW], t3 = t[3 * HW];
    int lab = 0; float best = t0;                 // first-index-wins (matches jnp.argmax)
    if (t1 > best) { best = t1; lab = 1; }
    if (t2 > best) { best = t2; lab = 2; }
    if (t3 > best) { best = t3; lab = 3; }

    unsigned mk = 0;
    if (p1 > 0.5f) mk |= 1u;
    if (p2 > 0.5f) mk |= 2u;
    if (p3 > 0.5f) mk |= 4u;
    if (lab == 1)  mk |= 8u;
    if (lab == 2)  mk |= 16u;
    if (lab == 3)  mk |= 32u;
    g_masks[idx] = (unsigned char)mk;

    int base = (b * 3) * HW + pix;
    g_p[base]          = p1;
    g_p[base + HW]     = p2;
    g_p[base + 2 * HW] = p3;

    // per-slice popcounts (for the valid = any() && !all() flag)
    __shared__ int scnt[6];
    if (threadIdx.x < 6) scnt[threadIdx.x] = 0;
    __syncthreads();
    #pragma unroll
    for (int bit = 0; bit < 6; bit++) {
        unsigned bal = __ballot_sync(0xffffffffu, (mk >> bit) & 1u);
        if ((threadIdx.x & 31) == 0) atomicAdd(&scnt[bit], __popc(bal));
    }
    __syncthreads();
    if (threadIdx.x < 3)      atomicAdd(&g_cnt[b * 3 + threadIdx.x], scnt[threadIdx.x]);
    else if (threadIdx.x < 6) atomicAdd(&g_cnt[NSLICE + b * 3 + threadIdx.x - 3], scnt[threadIdx.x]);
}

// -------- kernel 2: vertical capped-L1 distance (two sequential passes per column) --------
__global__ void __launch_bounds__(256) k_vert() {
    int bs  = blockIdx.x;          // 0..95 = f*NSLICE + s
    int f   = bs / NSLICE;
    int s   = bs % NSLICE;
    int col = threadIdx.x;
    int b   = s / 3, cc = s % 3;
    int bit = (f >= 2 ? 3 : 0) + cc;
    int invm = (f & 1);            // odd fields use the complement mask

    const unsigned char* mk = g_masks + (size_t)b * HW;
    unsigned short* gv = g_vert + ((size_t)f * NSLICE + s) * HW;

    // pass 1: top -> bottom
    int v = CAP;
    #pragma unroll 8
    for (int i = 0; i < HH; i++) {
        int m = (mk[i * WW + col] >> bit) & 1;
        m ^= invm;
        v = m ? min(v + 1, CAP) : 0;
        gv[i * WW + col] = (unsigned short)v;
    }
    // pass 2: bottom -> top  (mask==True <=> fwd != 0)
    v = CAP;
    #pragma unroll 8
    for (int i = HH - 1; i >= 0; i--) {
        int fw = gv[i * WW + col];
        v = (fw != 0) ? min(v + 1, CAP) : 0;
        gv[i * WW + col] = (unsigned short)min(fw, v);
    }
}

// exact outward search: min_k G[k] + (j-k)^2, early exit when d*d >= best
__device__ __forceinline__ int edt_search(const int* __restrict__ G, int j) {
    int best = G[j];
    #pragma unroll 4
    for (int d = 1; d < WW; d++) {
        int dd = d * d;
        if (dd >= best) break;
        int jm = j - d, jp = j + d;
        if (jm >= 0) best = min(best, G[jm] + dd);
        if (jp < WW) best = min(best, G[jp] + dd);
    }
    return best;
}

// -------- kernel 3: horizontal EDT (early exit) + fused loss reduction --------
__global__ void __launch_bounds__(256) k_row() {
    int s   = blockIdx.x >> 8;     // slice 0..23
    int row = blockIdx.x & 255;
    int j   = threadIdx.x;
    int b   = s / 3, cc = s % 3;

    __shared__ int G[4][WW];
    #pragma unroll
    for (int f = 0; f < 4; f++) {
        int g = g_vert[((size_t)f * NSLICE + s) * HW + row * WW + j];
        G[f][j] = g * g;
    }
    __syncthreads();

    int cp = g_cnt[s], ct = g_cnt[NSLICE + s];
    float vp = (cp > 0 && cp < HW) ? 1.0f : 0.0f;
    float vt = (ct > 0 && ct < HW) ? 1.0f : 0.0f;

    int dp = edt_search(G[0], j) + edt_search(G[1], j);
    int dt = edt_search(G[2], j) + edt_search(G[3], j);

    float p  = g_p[(size_t)s * HW + row * WW + j];
    unsigned mb = g_masks[(size_t)b * HW + row * WW + j];
    float tg = (float)((mb >> (3 + cc)) & 1u);
    float err = (p - tg) * (p - tg);
    float val = err * ((float)dp * vp + (float)dt * vt);

    // block reduction -> double atomic
    #pragma unroll
    for (int o = 16; o; o >>= 1) val += __shfl_down_sync(0xffffffffu, val, o);
    __shared__ float wsum[8];
    if ((threadIdx.x & 31) == 0) wsum[threadIdx.x >> 5] = val;
    __syncthreads();
    if (threadIdx.x == 0) {
        float ssum = 0.0f;
        #pragma unroll
        for (int w = 0; w < 8; w++) ssum += wsum[w];
        atomicAdd(&g_acc, (double)ssum);
    }
}

// -------- kernel 4: finalize --------
__global__ void k_final(float* out) {
    double mean = g_acc / (double)(NSLICE * HW);
    out[0] = (float)log(mean + 1.0);
}

extern "C" void kernel_launch(void* const* d_in, const int* in_sizes, int n_in,
                              void* d_out, int out_size) {
    const float* S = (const float*)d_in[0];   // preds_S (8,4,256,256)
    const float* T = (const float*)d_in[1];   // preds_T (8,4,256,256)
    (void)in_sizes; (void)n_in; (void)out_size;  // target (d_in[2]) unused by reference

    k_init<<<1, 64>>>();
    k_prep<<<NPIX / 256, 256>>>(S, T);
    k_vert<<<NFIELD * NSLICE, 256>>>();
    k_row<<<NSLICE * HH, 256>>>();
    k_final<<<1, 1>>>((float*)d_out);
}